// round 17
// baseline (speedup 1.0000x reference)
#include <cuda_runtime.h>
#include <cuda_bf16.h>

#define GS 256
#define PARAM 128
#define KC 32
#define I1 64
#define I2 32
#define PK 96
#define BB 4
#define EPS 1e-3f
#define NROWS (BB * GS)   // 1024
#define MAXY 64           // per-row nonzero capacity (mean 16, max ~40)
#define NBLK (NROWS / 8)  // 128 blocks, all resident (<=148 SMs)
#define BPB  (NBLK / BB)  // 32 blocks per batch

typedef unsigned long long u64;

// packed f32x2 helpers (sm_100+; FFMA2 only reachable via PTX)
__device__ __forceinline__ u64 pk2(float lo, float hi) {
    u64 r; asm("mov.b64 %0, {%1, %2};" : "=l"(r) : "f"(lo), "f"(hi)); return r;
}
__device__ __forceinline__ void upk2(u64 v, float& lo, float& hi) {
    asm("mov.b64 {%0, %1}, %2;" : "=f"(lo), "=f"(hi) : "l"(v));
}
__device__ __forceinline__ u64 fma2(u64 a, u64 b, u64 c) {
    u64 d; asm("fma.rn.f32x2 %0, %1, %2, %3;" : "=l"(d) : "l"(a), "l"(b), "l"(c)); return d;
}
__device__ __forceinline__ u64 add2(u64 a, u64 b) {
    u64 d; asm("add.rn.f32x2 %0, %1, %2;" : "=l"(d) : "l"(a), "l"(b)); return d;
}

// -------- scratch (device globals; no allocation allowed) --------
__device__ float d_C[NROWS * I1];        // per-row y-part, scale folded (cross-block)
__device__ unsigned int d_bar4[BB];      // per-batch monotonic barrier counters

// ---------------- single fused kernel ----------------
// 128 blocks x 8 warps, 8 rows/block.
//   pre-barrier : stage val -> layer-1 GEMM -> store C -> fence -> ARRIVE (batch ctr)
//   overlap     : fold W2/W3, mask compaction, A finalize, con copy
//   wait        : nanosleep spin until the 32 blocks of THIS batch arrived
//   post        : warp-per-row sparse MLP with packed f32x2 FMAs, direct var writes
__global__ void __launch_bounds__(256) fused_kernel(const float* __restrict__ mat,
                                                    const float* __restrict__ val,
                                                    const float* __restrict__ M1,
                                                    const float* __restrict__ B1,
                                                    const float* __restrict__ M2,
                                                    const float* __restrict__ B2,
                                                    const float* __restrict__ M3,
                                                    const float* __restrict__ B3,
                                                    const float* __restrict__ g1,
                                                    const float* __restrict__ b1,
                                                    const float* __restrict__ m1,
                                                    const float* __restrict__ v1,
                                                    const float* __restrict__ g2,
                                                    const float* __restrict__ b2,
                                                    const float* __restrict__ m2,
                                                    const float* __restrict__ v2,
                                                    const float* __restrict__ g3,
                                                    const float* __restrict__ b3,
                                                    const float* __restrict__ m3,
                                                    const float* __restrict__ v3,
                                                    float* __restrict__ out) {
    __shared__ float W2t[I2 * 68];         // 8.5 KB folded W2, transposed [col][j]
    __shared__ float4 W3p[I2 * 32];        // 16 KB folded W3, [j][lane]=cols 3l..3l+2
    __shared__ float b2s[I2];
    __shared__ float b3s[PK];
    __shared__ float axs[8][I1];           // 2 KB  A rows (block-local)
    __shared__ int ylist[8][MAXY];         // 2 KB
    __shared__ float yvs[8][MAXY];         // 2 KB
    __shared__ float4 s1q[8][I1];          // 8 KB  s1: 4 pairs packed per j
    __shared__ float4 s2q[8][I2];          // 4 KB  s2: 4 pairs packed per j
    __shared__ float vs[8][PARAM];         // 4 KB
    __shared__ float buf[2][8][I1];        // 4 KB

    int t = threadIdx.x;
    int lane = t & 31;
    int w = t >> 5;              // 0..7 = row within block
    int row0 = blockIdx.x * 8;
    int row = row0 + w;
    int b = row >> 8;            // == blockIdx.x >> 5
    int bat = blockIdx.x >> 5;   // batch 0..3 (32 blocks each)

    // ===== pre-barrier: stage val rows =====
    for (int i = t; i < 8 * PARAM; i += 256)
        vs[i >> 7][i & 127] = val[row0 * PARAM + i];
    __syncthreads();

    // ===== pre-barrier: layer-1 GEMM (both halves of M1) =====
    {
        int j = t & 63;
        int part = (t >> 6) & 1;          // 0 = M1[:128], 1 = M1[128:]
        int half = t >> 7;                // rows half*4 .. half*4+3
        float sumA[4] = {0.f, 0.f, 0.f, 0.f};
        float sumB[4] = {0.f, 0.f, 0.f, 0.f};
        const float* Mp = M1 + part * PARAM * I1 + j;
#pragma unroll
        for (int k = 0; k < PARAM; k += 8) {
            float a0 = Mp[(k + 0) * I1], a1 = Mp[(k + 1) * I1];
            float a2 = Mp[(k + 2) * I1], a3 = Mp[(k + 3) * I1];
            float c0 = Mp[(k + 4) * I1], c1 = Mp[(k + 5) * I1];
            float c2 = Mp[(k + 6) * I1], c3 = Mp[(k + 7) * I1];
#pragma unroll
            for (int r = 0; r < 4; r++) {
                float4 va = *(const float4*)&vs[half * 4 + r][k];
                float4 vb = *(const float4*)&vs[half * 4 + r][k + 4];
                sumA[r] = fmaf(va.x, a0, fmaf(va.y, a1, fmaf(va.z, a2, fmaf(va.w, a3, sumA[r]))));
                sumB[r] = fmaf(vb.x, c0, fmaf(vb.y, c1, fmaf(vb.z, c2, fmaf(vb.w, c3, sumB[r]))));
            }
        }
#pragma unroll
        for (int r = 0; r < 4; r++) buf[part][half * 4 + r][j] = sumA[r] + sumB[r];
        __syncthreads();
        // C to global NOW (the only cross-block data)
        if (part == 1) {
            float sc = g1[j] * rsqrtf(v1[j] + EPS);
#pragma unroll
            for (int r = 0; r < 4; r++) {
                int rr = half * 4 + r;
                d_C[(row0 + rr) * I1 + j] = buf[1][rr][j] * sc;
            }
        }
    }

    // ===== arrive on batch counter (release C writes) =====
    __threadfence();
    __syncthreads();
    if (t == 0) atomicAdd(&d_bar4[bat], 1u);

    // ===== overlap window: block-local prep while batch peers finish =====
    for (int i = t; i < I1 * I2; i += 256) {
        int col = i & 31, j = i >> 5;
        float s = g2[col] * rsqrtf(v2[col] + EPS);
        W2t[col * 68 + j] = M2[j * I2 + col] * s;
    }
    {
        float* W3f = (float*)W3p;
        for (int i = t; i < I2 * 128; i += 256) {
            int j = i >> 7, q = i & 127, l = q >> 2, d = q & 3;
            float vvv = 0.f;
            if (d < 3) {
                int col = 3 * l + d;
                vvv = M3[j * PK + col] * (g3[col] * rsqrtf(v3[col] + EPS));
            }
            W3f[i] = vvv;
        }
    }
    if (t < I2) {
        float s = g2[t] * rsqrtf(v2[t] + EPS);
        b2s[t] = B2[t] * s + (b2[t] - m2[t] * s);
    }
    if (t >= 128 && t < 128 + PK) {
        int k = t - 128;
        float s = g3[k] * rsqrtf(v3[k] + EPS);
        b3s[k] = B3[k] * s + (b3[k] - m3[k] * s);
    }
    // A finalize (block-local, from buf)
    {
        int j = t & 63;
        int part = (t >> 6) & 1;
        int half = t >> 7;
        if (part == 0) {
            float sc = g1[j] * rsqrtf(v1[j] + EPS);
            float bb = B1[j] * sc + (b1[j] - m1[j] * sc);
#pragma unroll
            for (int r = 0; r < 4; r++) {
                int rr = half * 4 + r;
                axs[rr][j] = (buf[0][rr][j] - buf[1][rr][j]) * sc + bb;
            }
        }
    }
    // per-warp mask compaction (deterministic ballot prefix); n4 stays in regs
    int n4;
    {
        int cnt = 0;
#pragma unroll
        for (int c = 0; c < GS / 32; c++) {
            int idx = c * 32 + lane;
            float mv = mat[row * GS + idx];
            unsigned msk = __ballot_sync(0xffffffffu, mv != 0.0f);
            if (mv != 0.0f) {
                int off = cnt + __popc(msk & ((1u << lane) - 1u));
                ylist[w][off] = idx;
                yvs[w][off] = mv;
            }
            cnt += __popc(msk);
        }
        n4 = (cnt + 3) & ~3;
        for (int k = cnt + lane; k < n4; k += 32) { ylist[w][k] = 0; yvs[w][k] = 0.f; }
    }
    // con copy (independent of everything)
    out[row * PARAM + lane] = vs[w][lane];
    __syncwarp();

    // ===== wait for the 32 blocks of this batch (nanosleep spin) =====
    __syncthreads();             // block-local prep done
    if (t == 0) {
        unsigned seen = atomicAdd(&d_bar4[bat], 0u);
        unsigned target = ((seen - 1u) / (unsigned)BPB + 1u) * (unsigned)BPB;
        while (*(volatile unsigned*)&d_bar4[bat] < target) { __nanosleep(64); }
    }
    __syncthreads();

    // ===== phase 2: warp-per-row sparse MLP (packed f32x2) =====
    float axl = axs[w][lane];
    float axh = axs[w][lane + 32];
    float b2l = b2s[lane];
    float b30 = b3s[3 * lane], b31 = b3s[3 * lane + 1], b32 = b3s[3 * lane + 2];
    float a0 = 0.f, a1 = 0.f, a2 = 0.f;

    const float* Cb = d_C + b * GS * I1;

    float cl[4], ch[4];
    if (n4 > 0) {
#pragma unroll
        for (int p = 0; p < 4; p++) {
            const float* cy = Cb + ylist[w][p] * I1;
            cl[p] = __ldg(cy + lane);
            ch[p] = __ldg(cy + lane + 32);
        }
    }

    for (int i0 = 0; i0 < n4; i0 += 4) {
        // layer 1: 4 pairs packed per j -> two STS.128
        s1q[w][lane] = make_float4(fmaxf(axl + cl[0], 0.f), fmaxf(axl + cl[1], 0.f),
                                   fmaxf(axl + cl[2], 0.f), fmaxf(axl + cl[3], 0.f));
        s1q[w][lane + 32] = make_float4(fmaxf(axh + ch[0], 0.f), fmaxf(axh + ch[1], 0.f),
                                        fmaxf(axh + ch[2], 0.f), fmaxf(axh + ch[3], 0.f));
        __syncwarp();
        // prefetch next batch's C rows (hides L2 latency under compute)
        if (i0 + 4 < n4) {
#pragma unroll
            for (int p = 0; p < 4; p++) {
                const float* cy = Cb + ylist[w][i0 + 4 + p] * I1;
                cl[p] = __ldg(cy + lane);
                ch[p] = __ldg(cy + lane + 32);
            }
        }
        // layer 2: lane = output col; packed (pair01, pair23), even/odd-q split chains.
        // Bias enters exactly ONE chain per pair-set (aA01 for pairs 0,1; aA23 for 2,3).
        u64 aA01 = pk2(b2l, b2l), aA23 = pk2(b2l, b2l);
        u64 aB01 = pk2(0.f, 0.f), aB23 = pk2(0.f, 0.f);
        const float4* w2v = (const float4*)&W2t[lane * 68];
        const float4* s1v = (const float4*)s1q[w];
#pragma unroll
        for (int q = 0; q < 16; q += 2) {
            float4 wa = w2v[q], wb = w2v[q + 1];
            float4 sa0 = s1v[4 * q + 0], sa1 = s1v[4 * q + 1];
            float4 sa2 = s1v[4 * q + 2], sa3 = s1v[4 * q + 3];
            float4 sb0 = s1v[4 * q + 4], sb1 = s1v[4 * q + 5];
            float4 sb2 = s1v[4 * q + 6], sb3 = s1v[4 * q + 7];
            u64 wx = pk2(wa.x, wa.x), wy = pk2(wa.y, wa.y);
            u64 wz = pk2(wa.z, wa.z), ww = pk2(wa.w, wa.w);
            aA01 = fma2(pk2(sa0.x, sa0.y), wx, aA01); aA23 = fma2(pk2(sa0.z, sa0.w), wx, aA23);
            aA01 = fma2(pk2(sa1.x, sa1.y), wy, aA01); aA23 = fma2(pk2(sa1.z, sa1.w), wy, aA23);
            aA01 = fma2(pk2(sa2.x, sa2.y), wz, aA01); aA23 = fma2(pk2(sa2.z, sa2.w), wz, aA23);
            aA01 = fma2(pk2(sa3.x, sa3.y), ww, aA01); aA23 = fma2(pk2(sa3.z, sa3.w), ww, aA23);
            u64 vx = pk2(wb.x, wb.x), vy = pk2(wb.y, wb.y);
            u64 vz = pk2(wb.z, wb.z), vw = pk2(wb.w, wb.w);
            aB01 = fma2(pk2(sb0.x, sb0.y), vx, aB01); aB23 = fma2(pk2(sb0.z, sb0.w), vx, aB23);
            aB01 = fma2(pk2(sb1.x, sb1.y), vy, aB01); aB23 = fma2(pk2(sb1.z, sb1.w), vy, aB23);
            aB01 = fma2(pk2(sb2.x, sb2.y), vz, aB01); aB23 = fma2(pk2(sb2.z, sb2.w), vz, aB23);
            aB01 = fma2(pk2(sb3.x, sb3.y), vw, aB01); aB23 = fma2(pk2(sb3.z, sb3.w), vw, aB23);
        }
        {
            float f0, f1, f2, f3;
            upk2(add2(aA01, aB01), f0, f1);
            upk2(add2(aA23, aB23), f2, f3);
            s2q[w][lane] = make_float4(fmaxf(f0, 0.f), fmaxf(f1, 0.f),
                                       fmaxf(f2, 0.f), fmaxf(f3, 0.f));
        }
        __syncwarp();
        // layer 3: lane owns output cols 3l..3l+2; 6 packed chains, bias in BOTH
        // pair-set chains (single chain per pair-set per output col).
        u64 ax01 = pk2(b30, b30), ax23 = pk2(b30, b30);
        u64 ay01 = pk2(b31, b31), ay23 = pk2(b31, b31);
        u64 az01 = pk2(b32, b32), az23 = pk2(b32, b32);
#pragma unroll
        for (int j = 0; j < I2; j++) {
            float4 s = s2q[w][j];
            float4 wv = W3p[j * 32 + lane];
            u64 u01 = pk2(s.x, s.y), u23 = pk2(s.z, s.w);
            u64 wx = pk2(wv.x, wv.x), wy = pk2(wv.y, wv.y), wz = pk2(wv.z, wv.z);
            ax01 = fma2(u01, wx, ax01); ax23 = fma2(u23, wx, ax23);
            ay01 = fma2(u01, wy, ay01); ay23 = fma2(u23, wy, ay23);
            az01 = fma2(u01, wz, az01); az23 = fma2(u23, wz, az23);
        }
        float m0 = yvs[w][i0], m1v = yvs[w][i0 + 1], m2v = yvs[w][i0 + 2], m3v = yvs[w][i0 + 3];
        {
            float p0, p1, p2, p3;
            upk2(ax01, p0, p1); upk2(ax23, p2, p3);
            a0 = fmaf(fmaxf(p0, 0.f), m0, a0); a0 = fmaf(fmaxf(p1, 0.f), m1v, a0);
            a0 = fmaf(fmaxf(p2, 0.f), m2v, a0); a0 = fmaf(fmaxf(p3, 0.f), m3v, a0);
            upk2(ay01, p0, p1); upk2(ay23, p2, p3);
            a1 = fmaf(fmaxf(p0, 0.f), m0, a1); a1 = fmaf(fmaxf(p1, 0.f), m1v, a1);
            a1 = fmaf(fmaxf(p2, 0.f), m2v, a1); a1 = fmaf(fmaxf(p3, 0.f), m3v, a1);
            upk2(az01, p0, p1); upk2(az23, p2, p3);
            a2 = fmaf(fmaxf(p0, 0.f), m0, a2); a2 = fmaf(fmaxf(p1, 0.f), m1v, a2);
            a2 = fmaf(fmaxf(p2, 0.f), m2v, a2); a2 = fmaf(fmaxf(p3, 0.f), m3v, a2);
        }
    }

    // ===== epilogue: var writes only (con already copied in overlap window) =====
    float* orow = out + row * PARAM;
    orow[KC + 3 * lane + 0] = fminf(fmaxf(a0 * (1.f / 16.f), -1.f), 1.f);
    orow[KC + 3 * lane + 1] = fminf(fmaxf(a1 * (1.f / 16.f), -1.f), 1.f);
    orow[KC + 3 * lane + 2] = fminf(fmaxf(a2 * (1.f / 16.f), -1.f), 1.f);
}

extern "C" void kernel_launch(void* const* d_in, const int* in_sizes, int n_in,
                              void* d_out, int out_size) {
    const float* mat = (const float*)d_in[0];
    const float* val = (const float*)d_in[1];
    const float* M1  = (const float*)d_in[2];
    const float* B1  = (const float*)d_in[3];
    const float* M2  = (const float*)d_in[4];
    const float* B2  = (const float*)d_in[5];
    const float* M3  = (const float*)d_in[6];
    const float* B3  = (const float*)d_in[7];
    const float* g1  = (const float*)d_in[8];
    const float* b1  = (const float*)d_in[9];
    const float* m1  = (const float*)d_in[10];
    const float* v1  = (const float*)d_in[11];
    const float* g2  = (const float*)d_in[12];
    const float* b2  = (const float*)d_in[13];
    const float* m2  = (const float*)d_in[14];
    const float* v2  = (const float*)d_in[15];
    const float* g3  = (const float*)d_in[16];
    const float* b3  = (const float*)d_in[17];
    const float* m3  = (const float*)d_in[18];
    const float* v3  = (const float*)d_in[19];
    float* out = (float*)d_out;

    fused_kernel<<<NBLK, 256>>>(mat, val, M1, B1, M2, B2, M3, B3,
                                g1, b1, m1, v1, g2, b2, m2, v2,
                                g3, b3, m3, v3, out);
}